// round 16
// baseline (speedup 1.0000x reference)
#include <cuda_runtime.h>
#include <cuda_bf16.h>
#include <math.h>
#include <stdint.h>

// Problem constants
constexpr int Bb = 4;
constexpr int Ss = 2048;
constexpr int Ee = 768;
constexpr int Hh = 12;
constexpr int Dd = 64;
constexpr int Mrows = Bb * Ss;      // 8192
constexpr int N_QKV = 3 * Ee;       // 2304
constexpr int Kdim = 768;

// bf16 scratch (device globals: no allocation allowed)
__device__ __nv_bfloat16 g_xh[(size_t)Mrows * Kdim];
__device__ __nv_bfloat16 g_xl[(size_t)Mrows * Kdim];
__device__ __nv_bfloat16 g_WaTh[(size_t)N_QKV * Kdim];   // [n][k]
__device__ __nv_bfloat16 g_WaTl[(size_t)N_QKV * Kdim];
__device__ __nv_bfloat16 g_WpTh[(size_t)Ee * Ee];        // [n][k]
__device__ __nv_bfloat16 g_WpTl[(size_t)Ee * Ee];
__device__ __nv_bfloat16 g_qh[(size_t)Bb * Hh * Ss * Dd];
__device__ __nv_bfloat16 g_ql[(size_t)Bb * Hh * Ss * Dd];
__device__ __nv_bfloat16 g_kh[(size_t)Bb * Hh * Ss * Dd];
__device__ __nv_bfloat16 g_kl[(size_t)Bb * Hh * Ss * Dd];
__device__ __nv_bfloat16 g_vth[(size_t)Bb * Hh * Dd * Ss];  // transposed [b,h,d,s]
__device__ __nv_bfloat16 g_vtl[(size_t)Bb * Hh * Dd * Ss];
__device__ __nv_bfloat16 g_yh[(size_t)Mrows * Ee];
__device__ __nv_bfloat16 g_yl[(size_t)Mrows * Ee];

// ---------------------------------------------------------------------------
// Shared helpers
// ---------------------------------------------------------------------------
constexpr int GBM = 128, GBN = 64, GBK = 32;
constexpr int A_LD  = GBK + 8;   // 40
constexpr int BT_LD = GBK + 8;   // 40
constexpr int ASZ = GBM * A_LD;  // 5120 bf16
constexpr int BSZ = GBN * BT_LD; // 2560 bf16
// dynamic smem layout (bf16 elems): Ah0 Ah1 Al0 Al1 Bh0 Bh1 Bl0 Bl1
constexpr size_t GEMM_SMEM_BYTES = (size_t)(4 * ASZ + 4 * BSZ) * 2;  // 61440

__device__ __forceinline__ uint32_t pack2(float v0, float v1) {
    __nv_bfloat162 t = __floats2bfloat162_rn(v0, v1);
    return *reinterpret_cast<uint32_t*>(&t);
}

__device__ __forceinline__ void split2(float v0, float v1, uint32_t& h, uint32_t& l) {
    const float h0 = __bfloat162float(__float2bfloat16(v0));
    const float h1 = __bfloat162float(__float2bfloat16(v1));
    h = pack2(h0, h1);
    l = pack2(v0 - h0, v1 - h1);
}

__device__ __forceinline__ void mma_bf16(float d[4],
                                         const uint32_t a[4],
                                         const uint32_t b[2]) {
    asm volatile(
        "mma.sync.aligned.m16n8k16.row.col.f32.bf16.bf16.f32 "
        "{%0,%1,%2,%3}, {%4,%5,%6,%7}, {%8,%9}, {%0,%1,%2,%3};\n"
        : "+f"(d[0]), "+f"(d[1]), "+f"(d[2]), "+f"(d[3])
        : "r"(a[0]), "r"(a[1]), "r"(a[2]), "r"(a[3]),
          "r"(b[0]), "r"(b[1]));
}

__device__ __forceinline__ void cp16(__nv_bfloat16* sptr, const __nv_bfloat16* gptr) {
    const uint32_t saddr = (uint32_t)__cvta_generic_to_shared(sptr);
    asm volatile("cp.async.cg.shared.global [%0], [%1], 16;\n"
                 :: "r"(saddr), "l"(gptr));
}
__device__ __forceinline__ void cp_commit() {
    asm volatile("cp.async.commit_group;\n");
}
__device__ __forceinline__ void cp_wait1() {
    asm volatile("cp.async.wait_group 1;\n" ::: "memory");
}
__device__ __forceinline__ void cp_wait0() {
    asm volatile("cp.async.wait_group 0;\n" ::: "memory");
}

// ---------------------------------------------------------------------------
// Prep kernel A: split x -> g_xh/g_xl. 8 elems/thread.
// ---------------------------------------------------------------------------
__global__ __launch_bounds__(256) void split_x_kernel(const float* __restrict__ x)
{
    const size_t base = ((size_t)blockIdx.x * 256 + threadIdx.x) * 8;
    const float4 a = *reinterpret_cast<const float4*>(x + base);
    const float4 c = *reinterpret_cast<const float4*>(x + base + 4);
    const float v[8] = {a.x, a.y, a.z, a.w, c.x, c.y, c.z, c.w};
    uint32_t hh[4], ll[4];
    #pragma unroll
    for (int q = 0; q < 4; q++) split2(v[2 * q], v[2 * q + 1], hh[q], ll[q]);
    *reinterpret_cast<uint4*>(g_xh + base) = make_uint4(hh[0], hh[1], hh[2], hh[3]);
    *reinterpret_cast<uint4*>(g_xl + base) = make_uint4(ll[0], ll[1], ll[2], ll[3]);
}

// ---------------------------------------------------------------------------
// Prep kernel B1: split + transpose W_attn -> g_WaTh/l [N_QKV][K]
// ---------------------------------------------------------------------------
__global__ __launch_bounds__(256) void split_wa_kernel(const float* __restrict__ W)
{
    __shared__ float tile[32][33];
    const int tx = threadIdx.x & 31;
    const int ty = threadIdx.x >> 5;
    const int n0 = blockIdx.x * 32;
    const int k0 = blockIdx.y * 32;

    #pragma unroll
    for (int r = ty; r < 32; r += 8)
        tile[r][tx] = W[(size_t)(k0 + r) * N_QKV + n0 + tx];
    __syncthreads();

    #pragma unroll
    for (int r = ty; r < 32; r += 8) {
        const float v = tile[tx][r];
        const float h = __bfloat162float(__float2bfloat16(v));
        g_WaTh[(size_t)(n0 + r) * Kdim + k0 + tx] = __float2bfloat16(h);
        g_WaTl[(size_t)(n0 + r) * Kdim + k0 + tx] = __float2bfloat16(v - h);
    }
}

// ---------------------------------------------------------------------------
// Prep kernel B2: split + transpose W_proj -> g_WpTh/l [E][K]
// ---------------------------------------------------------------------------
__global__ __launch_bounds__(256) void split_wp_kernel(const float* __restrict__ W)
{
    __shared__ float tile[32][33];
    const int tx = threadIdx.x & 31;
    const int ty = threadIdx.x >> 5;
    const int n0 = blockIdx.x * 32;
    const int k0 = blockIdx.y * 32;

    #pragma unroll
    for (int r = ty; r < 32; r += 8)
        tile[r][tx] = W[(size_t)(k0 + r) * Ee + n0 + tx];
    __syncthreads();

    #pragma unroll
    for (int r = ty; r < 32; r += 8) {
        const float v = tile[tx][r];
        const float h = __bfloat162float(__float2bfloat16(v));
        g_WpTh[(size_t)(n0 + r) * Kdim + k0 + tx] = __float2bfloat16(h);
        g_WpTl[(size_t)(n0 + r) * Kdim + k0 + tx] = __float2bfloat16(v - h);
    }
}

// ---------------------------------------------------------------------------
// Kernel 1: QKV GEMM — double-buffered cp.async pipeline.
// ---------------------------------------------------------------------------
__global__ __launch_bounds__(256) void qkv_gemm_kernel(const float* __restrict__ bias)
{
    extern __shared__ __nv_bfloat16 smg[];
    __nv_bfloat16* Ah[2] = { smg,            smg + ASZ };
    __nv_bfloat16* Al[2] = { smg + 2 * ASZ,  smg + 3 * ASZ };
    __nv_bfloat16* Bh[2] = { smg + 4 * ASZ,             smg + 4 * ASZ + BSZ };
    __nv_bfloat16* Bl[2] = { smg + 4 * ASZ + 2 * BSZ,   smg + 4 * ASZ + 3 * BSZ };

    const int tid = threadIdx.x;
    const int m0 = blockIdx.y * GBM;
    const int n0 = blockIdx.x * GBN;

    const int w    = tid >> 5;
    const int wm   = w >> 1;
    const int wn   = w & 1;
    const int lane = tid & 31;
    const int g    = lane >> 2;
    const int tg   = lane & 3;

    // per-thread copy coordinates
    const int ar0 = tid >> 2;            // A rows: ar0, ar0+64
    const int ac8 = tid & 3;
    const int br  = tid >> 2;            // B row 0..63
    const int bc8 = tid & 3;

    float acc[2][4][4] = {};
    constexpr int NIT = Kdim / GBK;      // 24

    // Prologue: stage 0 copy of tile 0
    {
        const int k0 = 0;
        #pragma unroll
        for (int p = 0; p < 2; p++) {
            const int r = ar0 + p * 64;
            const size_t goff = (size_t)(m0 + r) * Kdim + k0 + ac8 * 8;
            cp16(Ah[0] + r * A_LD + ac8 * 8, g_xh + goff);
            cp16(Al[0] + r * A_LD + ac8 * 8, g_xl + goff);
        }
        {
            const size_t goff = (size_t)(n0 + br) * Kdim + k0 + bc8 * 8;
            cp16(Bh[0] + br * BT_LD + bc8 * 8, g_WaTh + goff);
            cp16(Bl[0] + br * BT_LD + bc8 * 8, g_WaTl + goff);
        }
        cp_commit();
    }

    for (int it = 0; it < NIT; it++) {
        const int s = it & 1;
        // Issue next tile copy into the other buffer
        if (it + 1 < NIT) {
            const int k0 = (it + 1) * GBK;
            const int sn = (it + 1) & 1;
            #pragma unroll
            for (int p = 0; p < 2; p++) {
                const int r = ar0 + p * 64;
                const size_t goff = (size_t)(m0 + r) * Kdim + k0 + ac8 * 8;
                cp16(Ah[sn] + r * A_LD + ac8 * 8, g_xh + goff);
                cp16(Al[sn] + r * A_LD + ac8 * 8, g_xl + goff);
            }
            {
                const size_t goff = (size_t)(n0 + br) * Kdim + k0 + bc8 * 8;
                cp16(Bh[sn] + br * BT_LD + bc8 * 8, g_WaTh + goff);
                cp16(Bl[sn] + br * BT_LD + bc8 * 8, g_WaTl + goff);
            }
            cp_commit();
            cp_wait1();          // tile `it` ready (1 group still in flight)
        } else {
            cp_wait0();
        }
        __syncthreads();

        const __nv_bfloat16* cAh = Ah[s];
        const __nv_bfloat16* cAl = Al[s];
        const __nv_bfloat16* cBh = Bh[s];
        const __nv_bfloat16* cBl = Bl[s];

        #pragma unroll
        for (int ks = 0; ks < 2; ks++) {
            const int kk = ks * 16;
            uint32_t ahf[2][4], alf[2][4];
            #pragma unroll
            for (int i = 0; i < 2; i++) {
                const int brr = wm * 32 + i * 16;
                ahf[i][0] = *reinterpret_cast<const uint32_t*>(cAh + (brr + g)     * A_LD + kk + tg * 2);
                ahf[i][1] = *reinterpret_cast<const uint32_t*>(cAh + (brr + g + 8) * A_LD + kk + tg * 2);
                ahf[i][2] = *reinterpret_cast<const uint32_t*>(cAh + (brr + g)     * A_LD + kk + tg * 2 + 8);
                ahf[i][3] = *reinterpret_cast<const uint32_t*>(cAh + (brr + g + 8) * A_LD + kk + tg * 2 + 8);
                alf[i][0] = *reinterpret_cast<const uint32_t*>(cAl + (brr + g)     * A_LD + kk + tg * 2);
                alf[i][1] = *reinterpret_cast<const uint32_t*>(cAl + (brr + g + 8) * A_LD + kk + tg * 2);
                alf[i][2] = *reinterpret_cast<const uint32_t*>(cAl + (brr + g)     * A_LD + kk + tg * 2 + 8);
                alf[i][3] = *reinterpret_cast<const uint32_t*>(cAl + (brr + g + 8) * A_LD + kk + tg * 2 + 8);
            }
            uint32_t bhf[4][2], blf[4][2];
            #pragma unroll
            for (int j = 0; j < 4; j++) {
                const int n = wn * 32 + j * 8 + g;
                bhf[j][0] = *reinterpret_cast<const uint32_t*>(cBh + n * BT_LD + kk + tg * 2);
                bhf[j][1] = *reinterpret_cast<const uint32_t*>(cBh + n * BT_LD + kk + tg * 2 + 8);
                blf[j][0] = *reinterpret_cast<const uint32_t*>(cBl + n * BT_LD + kk + tg * 2);
                blf[j][1] = *reinterpret_cast<const uint32_t*>(cBl + n * BT_LD + kk + tg * 2 + 8);
            }
            #pragma unroll
            for (int i = 0; i < 2; i++)
                #pragma unroll
                for (int j = 0; j < 4; j++) {
                    mma_bf16(acc[i][j], ahf[i], bhf[j]);
                    mma_bf16(acc[i][j], ahf[i], blf[j]);
                    mma_bf16(acc[i][j], alf[i], bhf[j]);
                }
        }
        __syncthreads();   // protect buffer s from the copy issued at it+1
    }

    // Epilogue: bias + split + scatter (q/k packed bf16x2, v transposed)
    #pragma unroll
    for (int i = 0; i < 2; i++) {
        #pragma unroll
        for (int j = 0; j < 4; j++) {
            const int colb = n0 + wn * 32 + j * 8 + tg * 2;   // even
            const float b0 = bias[colb];
            const float b1 = bias[colb + 1];
            const int which = colb / Ee;
            const int e = colb - which * Ee;
            const int hh = e >> 6;
            const int d = e & 63;
            #pragma unroll
            for (int half = 0; half < 2; half++) {
                const int m = m0 + wm * 32 + i * 16 + g + half * 8;
                const int bb = m >> 11;
                const int s = m & 2047;
                const float v0 = acc[i][j][half * 2 + 0] + b0;
                const float v1 = acc[i][j][half * 2 + 1] + b1;
                if (which < 2) {
                    uint32_t hpk, lpk;
                    split2(v0, v1, hpk, lpk);
                    const size_t idx = (((size_t)(bb * Hh + hh)) * Ss + s) * Dd + d;
                    __nv_bfloat16* dh = (which == 0) ? g_qh : g_kh;
                    __nv_bfloat16* dl = (which == 0) ? g_ql : g_kl;
                    *reinterpret_cast<uint32_t*>(dh + idx) = hpk;
                    *reinterpret_cast<uint32_t*>(dl + idx) = lpk;
                } else {
                    const float h0 = __bfloat162float(__float2bfloat16(v0));
                    const float h1 = __bfloat162float(__float2bfloat16(v1));
                    const size_t idxT = (((size_t)(bb * Hh + hh)) * Dd + d) * Ss + s;
                    g_vth[idxT]      = __float2bfloat16(h0);
                    g_vtl[idxT]      = __float2bfloat16(v0 - h0);
                    g_vth[idxT + Ss] = __float2bfloat16(h1);
                    g_vtl[idxT + Ss] = __float2bfloat16(v1 - h1);
                }
            }
        }
    }
}

// ---------------------------------------------------------------------------
// Kernel 2: tensor-core flash attention (byte-identical to R15-passing)
// ---------------------------------------------------------------------------
constexpr int QROWS = 128;
constexpr int AT_LD = 72;   // 64 + 8 pad
constexpr int OFF_QH = 0;
constexpr int OFF_QL = OFF_QH + QROWS * AT_LD;
constexpr int OFF_KH = OFF_QL + QROWS * AT_LD;
constexpr int OFF_KL = OFF_KH + 64 * AT_LD;
constexpr int OFF_VH = OFF_KL + 64 * AT_LD;
constexpr int OFF_VL = OFF_VH + 64 * AT_LD;
constexpr size_t ATT_SMEM_BYTES = (size_t)(OFF_VL + 64 * AT_LD) * 2;  // 73728 B

__global__ __launch_bounds__(256) void attn_kernel(const int* __restrict__ att_mask)
{
    extern __shared__ __nv_bfloat16 smb[];
    __nv_bfloat16* Qh = smb + OFF_QH;
    __nv_bfloat16* Ql = smb + OFF_QL;
    __nv_bfloat16* Kh = smb + OFF_KH;
    __nv_bfloat16* Kl = smb + OFF_KL;
    __nv_bfloat16* Vh = smb + OFF_VH;   // [d][key]
    __nv_bfloat16* Vl = smb + OFF_VL;

    const int tid  = threadIdx.x;
    const int wp   = tid >> 5;
    const int lane = tid & 31;
    const int g    = lane >> 2;
    const int tg   = lane & 3;

    const int qb = blockIdx.x;
    const int h  = blockIdx.y;
    const int b  = blockIdx.z;
    const size_t head_base = ((size_t)(b * Hh + h)) * Ss * Dd;
    const size_t vt_base   = ((size_t)(b * Hh + h)) * Dd * Ss;
    const int q0 = qb * QROWS;

    #pragma unroll
    for (int p = 0; p < 4; p++) {
        const int id = p * 256 + tid;
        const int r = id >> 3;
        const int c8 = id & 7;
        const size_t goff = head_base + (size_t)(q0 + r) * Dd + c8 * 8;
        *reinterpret_cast<uint4*>(Qh + r * AT_LD + c8 * 8) =
            *reinterpret_cast<const uint4*>(g_qh + goff);
        *reinterpret_cast<uint4*>(Ql + r * AT_LD + c8 * 8) =
            *reinterpret_cast<const uint4*>(g_ql + goff);
    }

    float m0 = -INFINITY, m1 = -INFINITY, l0 = 0.0f, l1 = 0.0f;
    float acc_o[8][4] = {};

    const int jmax = 2 * qb + 1;
    for (int j = 0; j <= jmax; j++) {
        __syncthreads();
        #pragma unroll
        for (int p = 0; p < 2; p++) {
            const int id = p * 256 + tid;
            const int r = id >> 3;
            const int c8 = id & 7;
            const size_t goff = head_base + (size_t)(j * 64 + r) * Dd + c8 * 8;
            *reinterpret_cast<uint4*>(Kh + r * AT_LD + c8 * 8) =
                *reinterpret_cast<const uint4*>(g_kh + goff);
            *reinterpret_cast<uint4*>(Kl + r * AT_LD + c8 * 8) =
                *reinterpret_cast<const uint4*>(g_kl + goff);
        }
        #pragma unroll
        for (int p = 0; p < 2; p++) {
            const int id = p * 256 + tid;
            const int r = id >> 3;
            const int c8 = id & 7;
            const size_t goff = vt_base + (size_t)r * Ss + j * 64 + c8 * 8;
            *reinterpret_cast<uint4*>(Vh + r * AT_LD + c8 * 8) =
                *reinterpret_cast<const uint4*>(g_vth + goff);
            *reinterpret_cast<uint4*>(Vl + r * AT_LD + c8 * 8) =
                *reinterpret_cast<const uint4*>(g_vtl + goff);
        }
        __syncthreads();

        float s[8][4] = {};
        #pragma unroll
        for (int kb = 0; kb < 4; kb++) {
            const int kk = kb * 16;
            uint32_t ah[4], al[4];
            const int br = wp * 16;
            ah[0] = *reinterpret_cast<const uint32_t*>(Qh + (br + g)     * AT_LD + kk + tg * 2);
            ah[1] = *reinterpret_cast<const uint32_t*>(Qh + (br + g + 8) * AT_LD + kk + tg * 2);
            ah[2] = *reinterpret_cast<const uint32_t*>(Qh + (br + g)     * AT_LD + kk + tg * 2 + 8);
            ah[3] = *reinterpret_cast<const uint32_t*>(Qh + (br + g + 8) * AT_LD + kk + tg * 2 + 8);
            al[0] = *reinterpret_cast<const uint32_t*>(Ql + (br + g)     * AT_LD + kk + tg * 2);
            al[1] = *reinterpret_cast<const uint32_t*>(Ql + (br + g + 8) * AT_LD + kk + tg * 2);
            al[2] = *reinterpret_cast<const uint32_t*>(Ql + (br + g)     * AT_LD + kk + tg * 2 + 8);
            al[3] = *reinterpret_cast<const uint32_t*>(Ql + (br + g + 8) * AT_LD + kk + tg * 2 + 8);
            #pragma unroll
            for (int t = 0; t < 8; t++) {
                const int n = t * 8 + g;
                uint32_t bh[2], bl[2];
                bh[0] = *reinterpret_cast<const uint32_t*>(Kh + n * AT_LD + kk + tg * 2);
                bh[1] = *reinterpret_cast<const uint32_t*>(Kh + n * AT_LD + kk + tg * 2 + 8);
                bl[0] = *reinterpret_cast<const uint32_t*>(Kl + n * AT_LD + kk + tg * 2);
                bl[1] = *reinterpret_cast<const uint32_t*>(Kl + n * AT_LD + kk + tg * 2 + 8);
                mma_bf16(s[t], ah, bh);
                mma_bf16(s[t], ah, bl);
                mma_bf16(s[t], al, bh);
            }
        }

        const int r0 = q0 + wp * 16 + g;
        const int r1 = r0 + 8;
        #pragma unroll
        for (int t = 0; t < 8; t++) {
            const int col0 = j * 64 + t * 8 + tg * 2;
            const int col1 = col0 + 1;
            const int mk0 = att_mask[b * Ss + col0];
            const int mk1 = att_mask[b * Ss + col1];
            s[t][0] = (col0 <= r0 && mk0 != 0) ? s[t][0] * 0.125f : -INFINITY;
            s[t][1] = (col1 <= r0 && mk1 != 0) ? s[t][1] * 0.125f : -INFINITY;
            s[t][2] = (col0 <= r1 && mk0 != 0) ? s[t][2] * 0.125f : -INFINITY;
            s[t][3] = (col1 <= r1 && mk1 != 0) ? s[t][3] * 0.125f : -INFINITY;
        }

        float rm0 = -INFINITY, rm1 = -INFINITY;
        #pragma unroll
        for (int t = 0; t < 8; t++) {
            rm0 = fmaxf(rm0, fmaxf(s[t][0], s[t][1]));
            rm1 = fmaxf(rm1, fmaxf(s[t][2], s[t][3]));
        }
        rm0 = fmaxf(rm0, __shfl_xor_sync(0xffffffffu, rm0, 1));
        rm0 = fmaxf(rm0, __shfl_xor_sync(0xffffffffu, rm0, 2));
        rm1 = fmaxf(rm1, __shfl_xor_sync(0xffffffffu, rm1, 1));
        rm1 = fmaxf(rm1, __shfl_xor_sync(0xffffffffu, rm1, 2));

        const float mn0 = fmaxf(m0, rm0);
        const float mn1 = fmaxf(m1, rm1);
        const float a0 = __expf(m0 - mn0);
        const float a1 = __expf(m1 - mn1);

        float rs0 = 0.0f, rs1 = 0.0f;
        #pragma unroll
        for (int t = 0; t < 8; t++) {
            s[t][0] = __expf(s[t][0] - mn0);
            s[t][1] = __expf(s[t][1] - mn0);
            s[t][2] = __expf(s[t][2] - mn1);
            s[t][3] = __expf(s[t][3] - mn1);
            rs0 += s[t][0] + s[t][1];
            rs1 += s[t][2] + s[t][3];
        }
        rs0 += __shfl_xor_sync(0xffffffffu, rs0, 1);
        rs0 += __shfl_xor_sync(0xffffffffu, rs0, 2);
        rs1 += __shfl_xor_sync(0xffffffffu, rs1, 1);
        rs1 += __shfl_xor_sync(0xffffffffu, rs1, 2);

        l0 = l0 * a0 + rs0;
        l1 = l1 * a1 + rs1;
        m0 = mn0;
        m1 = mn1;
        #pragma unroll
        for (int t = 0; t < 8; t++) {
            acc_o[t][0] *= a0;
            acc_o[t][1] *= a0;
            acc_o[t][2] *= a1;
            acc_o[t][3] *= a1;
        }

        #pragma unroll
        for (int kb = 0; kb < 4; kb++) {
            const int t0 = 2 * kb, t1 = 2 * kb + 1;
            uint32_t pah[4], pal[4];
            split2(s[t0][0], s[t0][1], pah[0], pal[0]);
            split2(s[t0][2], s[t0][3], pah[1], pal[1]);
            split2(s[t1][0], s[t1][1], pah[2], pal[2]);
            split2(s[t1][2], s[t1][3], pah[3], pal[3]);
            #pragma unroll
            for (int t = 0; t < 8; t++) {
                const int n = t * 8 + g;
                uint32_t bh[2], bl[2];
                bh[0] = *reinterpret_cast<const uint32_t*>(Vh + n * AT_LD + kb * 16 + tg * 2);
                bh[1] = *reinterpret_cast<const uint32_t*>(Vh + n * AT_LD + kb * 16 + tg * 2 + 8);
                bl[0] = *reinterpret_cast<const uint32_t*>(Vl + n * AT_LD + kb * 16 + tg * 2);
                bl[1] = *reinterpret_cast<const uint32_t*>(Vl + n * AT_LD + kb * 16 + tg * 2 + 8);
                mma_bf16(acc_o[t], pah, bh);
                mma_bf16(acc_o[t], pah, bl);
                mma_bf16(acc_o[t], pal, bh);
            }
        }
    }

    const float inv0 = 1.0f / l0;
    const float inv1 = 1.0f / l1;
    const int r0g = q0 + wp * 16 + g;
    const size_t row0 = ((size_t)(b * Ss + r0g)) * Ee + h * 64;
    const size_t row1 = ((size_t)(b * Ss + r0g + 8)) * Ee + h * 64;
    #pragma unroll
    for (int t = 0; t < 8; t++) {
        const int c = t * 8 + tg * 2;
        uint32_t hpk, lpk;
        split2(acc_o[t][0] * inv0, acc_o[t][1] * inv0, hpk, lpk);
        *reinterpret_cast<uint32_t*>(g_yh + row0 + c) = hpk;
        *reinterpret_cast<uint32_t*>(g_yl + row0 + c) = lpk;
        split2(acc_o[t][2] * inv1, acc_o[t][3] * inv1, hpk, lpk);
        *reinterpret_cast<uint32_t*>(g_yh + row1 + c) = hpk;
        *reinterpret_cast<uint32_t*>(g_yl + row1 + c) = lpk;
    }
}

// ---------------------------------------------------------------------------
// Kernel 3: proj GEMM — double-buffered cp.async pipeline.
// ---------------------------------------------------------------------------
__global__ __launch_bounds__(256) void proj_gemm_kernel(
    const float* __restrict__ bias,
    float* __restrict__ out)
{
    extern __shared__ __nv_bfloat16 smg[];
    __nv_bfloat16* Ah[2] = { smg,            smg + ASZ };
    __nv_bfloat16* Al[2] = { smg + 2 * ASZ,  smg + 3 * ASZ };
    __nv_bfloat16* Bh[2] = { smg + 4 * ASZ,             smg + 4 * ASZ + BSZ };
    __nv_bfloat16* Bl[2] = { smg + 4 * ASZ + 2 * BSZ,   smg + 4 * ASZ + 3 * BSZ };

    const int tid = threadIdx.x;
    const int m0 = blockIdx.y * GBM;
    const int n0 = blockIdx.x * GBN;

    const int w    = tid >> 5;
    const int wm   = w >> 1;
    const int wn   = w & 1;
    const int lane = tid & 31;
    const int g    = lane >> 2;
    const int tg   = lane & 3;

    const int ar0 = tid >> 2;
    const int ac8 = tid & 3;
    const int br  = tid >> 2;
    const int bc8 = tid & 3;

    float acc[2][4][4] = {};
    constexpr int NIT = Kdim / GBK;

    {
        #pragma unroll
        for (int p = 0; p < 2; p++) {
            const int r = ar0 + p * 64;
            const size_t goff = (size_t)(m0 + r) * Kdim + ac8 * 8;
            cp16(Ah[0] + r * A_LD + ac8 * 8, g_yh + goff);
            cp16(Al[0] + r * A_LD + ac8 * 8, g_yl + goff);
        }
        {
            const size_t goff = (size_t)(n0 + br) * Kdim + bc8 * 8;
            cp16(Bh[0] + br * BT_LD + bc8 * 8, g_WpTh + goff);
            cp16(Bl[0] + br * BT_LD + bc8 * 8, g_WpTl + goff);
        }
        cp_commit();
    }

    for (int it = 0; it < NIT; it++) {
        const int s = it & 1;
        if (it + 1 < NIT) {
            const int k0 = (it + 1) * GBK;
            const int sn = (it + 1) & 1;
            #pragma unroll
            for (int p = 0; p < 2; p++) {
                const int r = ar0 + p * 64;
                const size_t goff = (size_t)(m0 + r) * Kdim + k0 + ac8 * 8;
                cp16(Ah[sn] + r * A_LD + ac8 * 8, g_yh + goff);
                cp16(Al[sn] + r * A_LD + ac8 * 8, g_yl + goff);
            }
            {
                const size_t goff = (size_t)(n0 + br) * Kdim + k0 + bc8 * 8;
                cp16(Bh[sn] + br * BT_LD + bc8 * 8, g_WpTh + goff);
                cp16(Bl[sn] + br * BT_LD + bc8 * 8, g_WpTl + goff);
            }
            cp_commit();
            cp_wait1();
        } else {
            cp_wait0();
        }
        __syncthreads();

        const __nv_bfloat16* cAh = Ah[s];
        const __nv_bfloat16* cAl = Al[s];
        const __nv_bfloat16* cBh = Bh[s];
        const __nv_bfloat16* cBl = Bl[s];

        #pragma unroll
        for (int ks = 0; ks < 2; ks++) {
            const int kk = ks * 16;
            uint32_t ahf[2][4], alf[2][4];
            #pragma unroll
            for (int i = 0; i < 2; i++) {
                const int brr = wm * 32 + i * 16;
                ahf[i][0] = *reinterpret_cast<const uint32_t*>(cAh + (brr + g)     * A_LD + kk + tg * 2);
                ahf[i][1] = *reinterpret_cast<const uint32_t*>(cAh + (brr + g + 8) * A_LD + kk + tg * 2);
                ahf[i][2] = *reinterpret_cast<const uint32_t*>(cAh + (brr + g)     * A_LD + kk + tg * 2 + 8);
                ahf[i][3] = *reinterpret_cast<const uint32_t*>(cAh + (brr + g + 8) * A_LD + kk + tg * 2 + 8);
                alf[i][0] = *reinterpret_cast<const uint32_t*>(cAl + (brr + g)     * A_LD + kk + tg * 2);
                alf[i][1] = *reinterpret_cast<const uint32_t*>(cAl + (brr + g + 8) * A_LD + kk + tg * 2);
                alf[i][2] = *reinterpret_cast<const uint32_t*>(cAl + (brr + g)     * A_LD + kk + tg * 2 + 8);
                alf[i][3] = *reinterpret_cast<const uint32_t*>(cAl + (brr + g + 8) * A_LD + kk + tg * 2 + 8);
            }
            uint32_t bhf[4][2], blf[4][2];
            #pragma unroll
            for (int j = 0; j < 4; j++) {
                const int n = wn * 32 + j * 8 + g;
                bhf[j][0] = *reinterpret_cast<const uint32_t*>(cBh + n * BT_LD + kk + tg * 2);
                bhf[j][1] = *reinterpret_cast<const uint32_t*>(cBh + n * BT_LD + kk + tg * 2 + 8);
                blf[j][0] = *reinterpret_cast<const uint32_t*>(cBl + n * BT_LD + kk + tg * 2);
                blf[j][1] = *reinterpret_cast<const uint32_t*>(cBl + n * BT_LD + kk + tg * 2 + 8);
            }
            #pragma unroll
            for (int i = 0; i < 2; i++)
                #pragma unroll
                for (int j = 0; j < 4; j++) {
                    mma_bf16(acc[i][j], ahf[i], bhf[j]);
                    mma_bf16(acc[i][j], ahf[i], blf[j]);
                    mma_bf16(acc[i][j], alf[i], bhf[j]);
                }
        }
        __syncthreads();
    }

    #pragma unroll
    for (int i = 0; i < 2; i++) {
        #pragma unroll
        for (int j = 0; j < 4; j++) {
            const int colb = n0 + wn * 32 + j * 8 + tg * 2;
            #pragma unroll
            for (int e4 = 0; e4 < 4; e4++) {
                const int m = m0 + wm * 32 + i * 16 + g + (e4 >= 2 ? 8 : 0);
                const int n = colb + (e4 & 1);
                out[(size_t)m * Ee + n] = acc[i][j][e4] + bias[n];
            }
        }
    }
}

// ---------------------------------------------------------------------------
// Launch
// ---------------------------------------------------------------------------
extern "C" void kernel_launch(void* const* d_in, const int* in_sizes, int n_in,
                              void* d_out, int out_size)
{
    const float* x      = (const float*)d_in[0];  // [B,S,E]
    const float* W_attn = (const float*)d_in[1];  // [E,3E]
    const float* b_attn = (const float*)d_in[2];  // [3E]
    const float* W_proj = (const float*)d_in[3];  // [E,E]
    const float* b_proj = (const float*)d_in[4];  // [E]
    const int* att_mask = (const int*)d_in[5];    // [B,S]
    float* out = (float*)d_out;

    cudaFuncSetAttribute(attn_kernel,
                         cudaFuncAttributeMaxDynamicSharedMemorySize,
                         (int)ATT_SMEM_BYTES);
    cudaFuncSetAttribute(qkv_gemm_kernel,
                         cudaFuncAttributeMaxDynamicSharedMemorySize,
                         (int)GEMM_SMEM_BYTES);
    cudaFuncSetAttribute(proj_gemm_kernel,
                         cudaFuncAttributeMaxDynamicSharedMemorySize,
                         (int)GEMM_SMEM_BYTES);

    split_x_kernel<<<(Mrows * Kdim) / 2048, 256>>>(x);
    {
        dim3 grid(N_QKV / 32, Kdim / 32);      // 72 x 24
        split_wa_kernel<<<grid, 256>>>(W_attn);
    }
    {
        dim3 grid(Ee / 32, Kdim / 32);         // 24 x 24
        split_wp_kernel<<<grid, 256>>>(W_proj);
    }
    {
        dim3 grid(N_QKV / GBN, Mrows / GBM);   // 36 x 64
        qkv_gemm_kernel<<<grid, 256, GEMM_SMEM_BYTES>>>(b_attn);
    }
    {
        dim3 grid(Ss / QROWS, Hh, Bb);         // 16 x 12 x 4
        attn_kernel<<<grid, 256, ATT_SMEM_BYTES>>>(att_mask);
    }
    {
        dim3 grid(Ee / GBN, Mrows / GBM);      // 12 x 64
        proj_gemm_kernel<<<grid, 256, GEMM_SMEM_BYTES>>>(b_proj, out);
    }
}

// round 17
// speedup vs baseline: 1.5690x; 1.5690x over previous
#include <cuda_runtime.h>
#include <cuda_bf16.h>
#include <math.h>
#include <stdint.h>

// Problem constants
constexpr int Bb = 4;
constexpr int Ss = 2048;
constexpr int Ee = 768;
constexpr int Hh = 12;
constexpr int Dd = 64;
constexpr int Mrows = Bb * Ss;      // 8192
constexpr int N_QKV = 3 * Ee;       // 2304
constexpr int Kdim = 768;

// bf16 scratch (device globals: no allocation allowed)
__device__ __nv_bfloat16 g_xh[(size_t)Mrows * Kdim];
__device__ __nv_bfloat16 g_xl[(size_t)Mrows * Kdim];
__device__ __nv_bfloat16 g_WaTh[(size_t)N_QKV * Kdim];   // [n][k]
__device__ __nv_bfloat16 g_WaTl[(size_t)N_QKV * Kdim];
__device__ __nv_bfloat16 g_WpTh[(size_t)Ee * Ee];        // [n][k]
__device__ __nv_bfloat16 g_WpTl[(size_t)Ee * Ee];
__device__ __nv_bfloat16 g_qh[(size_t)Bb * Hh * Ss * Dd];
__device__ __nv_bfloat16 g_ql[(size_t)Bb * Hh * Ss * Dd];
__device__ __nv_bfloat16 g_kh[(size_t)Bb * Hh * Ss * Dd];
__device__ __nv_bfloat16 g_kl[(size_t)Bb * Hh * Ss * Dd];
__device__ __nv_bfloat16 g_vth[(size_t)Bb * Hh * Dd * Ss];  // transposed [b,h,d,s]
__device__ __nv_bfloat16 g_vtl[(size_t)Bb * Hh * Dd * Ss];
__device__ __nv_bfloat16 g_yh[(size_t)Mrows * Ee];
__device__ __nv_bfloat16 g_yl[(size_t)Mrows * Ee];

// ---------------------------------------------------------------------------
// Shared helpers
// ---------------------------------------------------------------------------
constexpr int GBM = 128, GBN = 64, GBK = 32;
constexpr int A_LD  = GBK + 8;   // 40
constexpr int BT_LD = GBK + 8;   // 40

__device__ __forceinline__ uint32_t pack2(float v0, float v1) {
    __nv_bfloat162 t = __floats2bfloat162_rn(v0, v1);
    return *reinterpret_cast<uint32_t*>(&t);
}

__device__ __forceinline__ void split2(float v0, float v1, uint32_t& h, uint32_t& l) {
    const float h0 = __bfloat162float(__float2bfloat16(v0));
    const float h1 = __bfloat162float(__float2bfloat16(v1));
    h = pack2(h0, h1);
    l = pack2(v0 - h0, v1 - h1);
}

__device__ __forceinline__ void mma_bf16(float d[4],
                                         const uint32_t a[4],
                                         const uint32_t b[2]) {
    asm volatile(
        "mma.sync.aligned.m16n8k16.row.col.f32.bf16.bf16.f32 "
        "{%0,%1,%2,%3}, {%4,%5,%6,%7}, {%8,%9}, {%0,%1,%2,%3};\n"
        : "+f"(d[0]), "+f"(d[1]), "+f"(d[2]), "+f"(d[3])
        : "r"(a[0]), "r"(a[1]), "r"(a[2]), "r"(a[3]),
          "r"(b[0]), "r"(b[1]));
}

// ---------------------------------------------------------------------------
// Prep kernel A: split x -> g_xh/g_xl. 8 elems/thread.
// ---------------------------------------------------------------------------
__global__ __launch_bounds__(256) void split_x_kernel(const float* __restrict__ x)
{
    const size_t base = ((size_t)blockIdx.x * 256 + threadIdx.x) * 8;
    const float4 a = *reinterpret_cast<const float4*>(x + base);
    const float4 c = *reinterpret_cast<const float4*>(x + base + 4);
    const float v[8] = {a.x, a.y, a.z, a.w, c.x, c.y, c.z, c.w};
    uint32_t hh[4], ll[4];
    #pragma unroll
    for (int q = 0; q < 4; q++) split2(v[2 * q], v[2 * q + 1], hh[q], ll[q]);
    *reinterpret_cast<uint4*>(g_xh + base) = make_uint4(hh[0], hh[1], hh[2], hh[3]);
    *reinterpret_cast<uint4*>(g_xl + base) = make_uint4(ll[0], ll[1], ll[2], ll[3]);
}

// ---------------------------------------------------------------------------
// Prep kernel B1: split + transpose W_attn -> g_WaTh/l [N_QKV][K]
// ---------------------------------------------------------------------------
__global__ __launch_bounds__(256) void split_wa_kernel(const float* __restrict__ W)
{
    __shared__ float tile[32][33];
    const int tx = threadIdx.x & 31;
    const int ty = threadIdx.x >> 5;
    const int n0 = blockIdx.x * 32;
    const int k0 = blockIdx.y * 32;

    #pragma unroll
    for (int r = ty; r < 32; r += 8)
        tile[r][tx] = W[(size_t)(k0 + r) * N_QKV + n0 + tx];
    __syncthreads();

    #pragma unroll
    for (int r = ty; r < 32; r += 8) {
        const float v = tile[tx][r];
        const float h = __bfloat162float(__float2bfloat16(v));
        g_WaTh[(size_t)(n0 + r) * Kdim + k0 + tx] = __float2bfloat16(h);
        g_WaTl[(size_t)(n0 + r) * Kdim + k0 + tx] = __float2bfloat16(v - h);
    }
}

// ---------------------------------------------------------------------------
// Prep kernel B2: split + transpose W_proj -> g_WpTh/l [E][K]
// ---------------------------------------------------------------------------
__global__ __launch_bounds__(256) void split_wp_kernel(const float* __restrict__ W)
{
    __shared__ float tile[32][33];
    const int tx = threadIdx.x & 31;
    const int ty = threadIdx.x >> 5;
    const int n0 = blockIdx.x * 32;
    const int k0 = blockIdx.y * 32;

    #pragma unroll
    for (int r = ty; r < 32; r += 8)
        tile[r][tx] = W[(size_t)(k0 + r) * Ee + n0 + tx];
    __syncthreads();

    #pragma unroll
    for (int r = ty; r < 32; r += 8) {
        const float v = tile[tx][r];
        const float h = __bfloat162float(__float2bfloat16(v));
        g_WpTh[(size_t)(n0 + r) * Kdim + k0 + tx] = __float2bfloat16(h);
        g_WpTl[(size_t)(n0 + r) * Kdim + k0 + tx] = __float2bfloat16(v - h);
    }
}

// ---------------------------------------------------------------------------
// Kernel 1: QKV GEMM — register-staged prefetch (LDG -> regs -> STS).
// ---------------------------------------------------------------------------
__global__ __launch_bounds__(256) void qkv_gemm_kernel(const float* __restrict__ bias)
{
    __shared__ __nv_bfloat16 Ah[GBM * A_LD];
    __shared__ __nv_bfloat16 Al[GBM * A_LD];
    __shared__ __nv_bfloat16 Bth[GBN * BT_LD];
    __shared__ __nv_bfloat16 Btl[GBN * BT_LD];

    const int tid = threadIdx.x;
    const int m0 = blockIdx.y * GBM;
    const int n0 = blockIdx.x * GBN;

    const int w    = tid >> 5;
    const int wm   = w >> 1;
    const int wn   = w & 1;
    const int lane = tid & 31;
    const int g    = lane >> 2;
    const int tg   = lane & 3;

    // copy coordinates: A rows ar, ar+64; B row br. 8 bf16 per uint4.
    const int ar  = tid >> 2;        // 0..63
    const int ac8 = tid & 3;
    const int br  = tid >> 2;
    const int bc8 = tid & 3;

    float acc[2][4][4] = {};
    constexpr int NIT = Kdim / GBK;  // 24

    uint4 rAh0, rAh1, rAl0, rAl1, rBh, rBl;
    // Prologue: load tile 0 into registers
    {
        const size_t a0 = (size_t)(m0 + ar) * Kdim + ac8 * 8;
        const size_t a1 = (size_t)(m0 + ar + 64) * Kdim + ac8 * 8;
        rAh0 = *reinterpret_cast<const uint4*>(g_xh + a0);
        rAh1 = *reinterpret_cast<const uint4*>(g_xh + a1);
        rAl0 = *reinterpret_cast<const uint4*>(g_xl + a0);
        rAl1 = *reinterpret_cast<const uint4*>(g_xl + a1);
        const size_t bo = (size_t)(n0 + br) * Kdim + bc8 * 8;
        rBh = *reinterpret_cast<const uint4*>(g_WaTh + bo);
        rBl = *reinterpret_cast<const uint4*>(g_WaTl + bo);
    }

    for (int it = 0; it < NIT; it++) {
        __syncthreads();   // previous mma done reading smem
        *reinterpret_cast<uint4*>(Ah + ar * A_LD + ac8 * 8)        = rAh0;
        *reinterpret_cast<uint4*>(Ah + (ar + 64) * A_LD + ac8 * 8) = rAh1;
        *reinterpret_cast<uint4*>(Al + ar * A_LD + ac8 * 8)        = rAl0;
        *reinterpret_cast<uint4*>(Al + (ar + 64) * A_LD + ac8 * 8) = rAl1;
        *reinterpret_cast<uint4*>(Bth + br * BT_LD + bc8 * 8)      = rBh;
        *reinterpret_cast<uint4*>(Btl + br * BT_LD + bc8 * 8)      = rBl;
        __syncthreads();

        // Prefetch next tile into registers (latency hidden by mma below)
        if (it + 1 < NIT) {
            const int k0 = (it + 1) * GBK;
            const size_t a0 = (size_t)(m0 + ar) * Kdim + k0 + ac8 * 8;
            const size_t a1 = (size_t)(m0 + ar + 64) * Kdim + k0 + ac8 * 8;
            rAh0 = *reinterpret_cast<const uint4*>(g_xh + a0);
            rAh1 = *reinterpret_cast<const uint4*>(g_xh + a1);
            rAl0 = *reinterpret_cast<const uint4*>(g_xl + a0);
            rAl1 = *reinterpret_cast<const uint4*>(g_xl + a1);
            const size_t bo = (size_t)(n0 + br) * Kdim + k0 + bc8 * 8;
            rBh = *reinterpret_cast<const uint4*>(g_WaTh + bo);
            rBl = *reinterpret_cast<const uint4*>(g_WaTl + bo);
        }

        #pragma unroll
        for (int ks = 0; ks < 2; ks++) {
            const int kk = ks * 16;
            uint32_t ahf[2][4], alf[2][4];
            #pragma unroll
            for (int i = 0; i < 2; i++) {
                const int brr = wm * 32 + i * 16;
                ahf[i][0] = *reinterpret_cast<const uint32_t*>(Ah + (brr + g)     * A_LD + kk + tg * 2);
                ahf[i][1] = *reinterpret_cast<const uint32_t*>(Ah + (brr + g + 8) * A_LD + kk + tg * 2);
                ahf[i][2] = *reinterpret_cast<const uint32_t*>(Ah + (brr + g)     * A_LD + kk + tg * 2 + 8);
                ahf[i][3] = *reinterpret_cast<const uint32_t*>(Ah + (brr + g + 8) * A_LD + kk + tg * 2 + 8);
                alf[i][0] = *reinterpret_cast<const uint32_t*>(Al + (brr + g)     * A_LD + kk + tg * 2);
                alf[i][1] = *reinterpret_cast<const uint32_t*>(Al + (brr + g + 8) * A_LD + kk + tg * 2);
                alf[i][2] = *reinterpret_cast<const uint32_t*>(Al + (brr + g)     * A_LD + kk + tg * 2 + 8);
                alf[i][3] = *reinterpret_cast<const uint32_t*>(Al + (brr + g + 8) * A_LD + kk + tg * 2 + 8);
            }
            uint32_t bhf[4][2], blf[4][2];
            #pragma unroll
            for (int j = 0; j < 4; j++) {
                const int n = wn * 32 + j * 8 + g;
                bhf[j][0] = *reinterpret_cast<const uint32_t*>(Bth + n * BT_LD + kk + tg * 2);
                bhf[j][1] = *reinterpret_cast<const uint32_t*>(Bth + n * BT_LD + kk + tg * 2 + 8);
                blf[j][0] = *reinterpret_cast<const uint32_t*>(Btl + n * BT_LD + kk + tg * 2);
                blf[j][1] = *reinterpret_cast<const uint32_t*>(Btl + n * BT_LD + kk + tg * 2 + 8);
            }
            #pragma unroll
            for (int i = 0; i < 2; i++)
                #pragma unroll
                for (int j = 0; j < 4; j++) {
                    mma_bf16(acc[i][j], ahf[i], bhf[j]);
                    mma_bf16(acc[i][j], ahf[i], blf[j]);
                    mma_bf16(acc[i][j], alf[i], bhf[j]);
                }
        }
    }

    // Epilogue: bias + split + scatter (q/k packed bf16x2, v transposed)
    #pragma unroll
    for (int i = 0; i < 2; i++) {
        #pragma unroll
        for (int j = 0; j < 4; j++) {
            const int colb = n0 + wn * 32 + j * 8 + tg * 2;   // even
            const float b0 = bias[colb];
            const float b1 = bias[colb + 1];
            const int which = colb / Ee;
            const int e = colb - which * Ee;
            const int hh = e >> 6;
            const int d = e & 63;
            #pragma unroll
            for (int half = 0; half < 2; half++) {
                const int m = m0 + wm * 32 + i * 16 + g + half * 8;
                const int bb = m >> 11;
                const int s = m & 2047;
                const float v0 = acc[i][j][half * 2 + 0] + b0;
                const float v1 = acc[i][j][half * 2 + 1] + b1;
                if (which < 2) {
                    uint32_t hpk, lpk;
                    split2(v0, v1, hpk, lpk);
                    const size_t idx = (((size_t)(bb * Hh + hh)) * Ss + s) * Dd + d;
                    __nv_bfloat16* dh = (which == 0) ? g_qh : g_kh;
                    __nv_bfloat16* dl = (which == 0) ? g_ql : g_kl;
                    *reinterpret_cast<uint32_t*>(dh + idx) = hpk;
                    *reinterpret_cast<uint32_t*>(dl + idx) = lpk;
                } else {
                    const float h0 = __bfloat162float(__float2bfloat16(v0));
                    const float h1 = __bfloat162float(__float2bfloat16(v1));
                    const size_t idxT = (((size_t)(bb * Hh + hh)) * Dd + d) * Ss + s;
                    g_vth[idxT]      = __float2bfloat16(h0);
                    g_vtl[idxT]      = __float2bfloat16(v0 - h0);
                    g_vth[idxT + Ss] = __float2bfloat16(h1);
                    g_vtl[idxT + Ss] = __float2bfloat16(v1 - h1);
                }
            }
        }
    }
}

// ---------------------------------------------------------------------------
// Kernel 2: tensor-core flash attention (byte-identical to R15-passing)
// ---------------------------------------------------------------------------
constexpr int QROWS = 128;
constexpr int AT_LD = 72;   // 64 + 8 pad
constexpr int OFF_QH = 0;
constexpr int OFF_QL = OFF_QH + QROWS * AT_LD;
constexpr int OFF_KH = OFF_QL + QROWS * AT_LD;
constexpr int OFF_KL = OFF_KH + 64 * AT_LD;
constexpr int OFF_VH = OFF_KL + 64 * AT_LD;
constexpr int OFF_VL = OFF_VH + 64 * AT_LD;
constexpr size_t ATT_SMEM_BYTES = (size_t)(OFF_VL + 64 * AT_LD) * 2;  // 73728 B

__global__ __launch_bounds__(256) void attn_kernel(const int* __restrict__ att_mask)
{
    extern __shared__ __nv_bfloat16 smb[];
    __nv_bfloat16* Qh = smb + OFF_QH;
    __nv_bfloat16* Ql = smb + OFF_QL;
    __nv_bfloat16* Kh = smb + OFF_KH;
    __nv_bfloat16* Kl = smb + OFF_KL;
    __nv_bfloat16* Vh = smb + OFF_VH;   // [d][key]
    __nv_bfloat16* Vl = smb + OFF_VL;

    const int tid  = threadIdx.x;
    const int wp   = tid >> 5;
    const int lane = tid & 31;
    const int g    = lane >> 2;
    const int tg   = lane & 3;

    const int qb = blockIdx.x;
    const int h  = blockIdx.y;
    const int b  = blockIdx.z;
    const size_t head_base = ((size_t)(b * Hh + h)) * Ss * Dd;
    const size_t vt_base   = ((size_t)(b * Hh + h)) * Dd * Ss;
    const int q0 = qb * QROWS;

    #pragma unroll
    for (int p = 0; p < 4; p++) {
        const int id = p * 256 + tid;
        const int r = id >> 3;
        const int c8 = id & 7;
        const size_t goff = head_base + (size_t)(q0 + r) * Dd + c8 * 8;
        *reinterpret_cast<uint4*>(Qh + r * AT_LD + c8 * 8) =
            *reinterpret_cast<const uint4*>(g_qh + goff);
        *reinterpret_cast<uint4*>(Ql + r * AT_LD + c8 * 8) =
            *reinterpret_cast<const uint4*>(g_ql + goff);
    }

    float m0 = -INFINITY, m1 = -INFINITY, l0 = 0.0f, l1 = 0.0f;
    float acc_o[8][4] = {};

    const int jmax = 2 * qb + 1;
    for (int j = 0; j <= jmax; j++) {
        __syncthreads();
        #pragma unroll
        for (int p = 0; p < 2; p++) {
            const int id = p * 256 + tid;
            const int r = id >> 3;
            const int c8 = id & 7;
            const size_t goff = head_base + (size_t)(j * 64 + r) * Dd + c8 * 8;
            *reinterpret_cast<uint4*>(Kh + r * AT_LD + c8 * 8) =
                *reinterpret_cast<const uint4*>(g_kh + goff);
            *reinterpret_cast<uint4*>(Kl + r * AT_LD + c8 * 8) =
                *reinterpret_cast<const uint4*>(g_kl + goff);
        }
        #pragma unroll
        for (int p = 0; p < 2; p++) {
            const int id = p * 256 + tid;
            const int r = id >> 3;
            const int c8 = id & 7;
            const size_t goff = vt_base + (size_t)r * Ss + j * 64 + c8 * 8;
            *reinterpret_cast<uint4*>(Vh + r * AT_LD + c8 * 8) =
                *reinterpret_cast<const uint4*>(g_vth + goff);
            *reinterpret_cast<uint4*>(Vl + r * AT_LD + c8 * 8) =
                *reinterpret_cast<const uint4*>(g_vtl + goff);
        }
        __syncthreads();

        float s[8][4] = {};
        #pragma unroll
        for (int kb = 0; kb < 4; kb++) {
            const int kk = kb * 16;
            uint32_t ah[4], al[4];
            const int br = wp * 16;
            ah[0] = *reinterpret_cast<const uint32_t*>(Qh + (br + g)     * AT_LD + kk + tg * 2);
            ah[1] = *reinterpret_cast<const uint32_t*>(Qh + (br + g + 8) * AT_LD + kk + tg * 2);
            ah[2] = *reinterpret_cast<const uint32_t*>(Qh + (br + g)     * AT_LD + kk + tg * 2 + 8);
            ah[3] = *reinterpret_cast<const uint32_t*>(Qh + (br + g + 8) * AT_LD + kk + tg * 2 + 8);
            al[0] = *reinterpret_cast<const uint32_t*>(Ql + (br + g)     * AT_LD + kk + tg * 2);
            al[1] = *reinterpret_cast<const uint32_t*>(Ql + (br + g + 8) * AT_LD + kk + tg * 2);
            al[2] = *reinterpret_cast<const uint32_t*>(Ql + (br + g)     * AT_LD + kk + tg * 2 + 8);
            al[3] = *reinterpret_cast<const uint32_t*>(Ql + (br + g + 8) * AT_LD + kk + tg * 2 + 8);
            #pragma unroll
            for (int t = 0; t < 8; t++) {
                const int n = t * 8 + g;
                uint32_t bh[2], bl[2];
                bh[0] = *reinterpret_cast<const uint32_t*>(Kh + n * AT_LD + kk + tg * 2);
                bh[1] = *reinterpret_cast<const uint32_t*>(Kh + n * AT_LD + kk + tg * 2 + 8);
                bl[0] = *reinterpret_cast<const uint32_t*>(Kl + n * AT_LD + kk + tg * 2);
                bl[1] = *reinterpret_cast<const uint32_t*>(Kl + n * AT_LD + kk + tg * 2 + 8);
                mma_bf16(s[t], ah, bh);
                mma_bf16(s[t], ah, bl);
                mma_bf16(s[t], al, bh);
            }
        }

        const int r0 = q0 + wp * 16 + g;
        const int r1 = r0 + 8;
        #pragma unroll
        for (int t = 0; t < 8; t++) {
            const int col0 = j * 64 + t * 8 + tg * 2;
            const int col1 = col0 + 1;
            const int mk0 = att_mask[b * Ss + col0];
            const int mk1 = att_mask[b * Ss + col1];
            s[t][0] = (col0 <= r0 && mk0 != 0) ? s[t][0] * 0.125f : -INFINITY;
            s[t][1] = (col1 <= r0 && mk1 != 0) ? s[t][1] * 0.125f : -INFINITY;
            s[t][2] = (col0 <= r1 && mk0 != 0) ? s[t][2] * 0.125f : -INFINITY;
            s[t][3] = (col1 <= r1 && mk1 != 0) ? s[t][3] * 0.125f : -INFINITY;
        }

        float rm0 = -INFINITY, rm1 = -INFINITY;
        #pragma unroll
        for (int t = 0; t < 8; t++) {
            rm0 = fmaxf(rm0, fmaxf(s[t][0], s[t][1]));
            rm1 = fmaxf(rm1, fmaxf(s[t][2], s[t][3]));
        }
        rm0 = fmaxf(rm0, __shfl_xor_sync(0xffffffffu, rm0, 1));
        rm0 = fmaxf(rm0, __shfl_xor_sync(0xffffffffu, rm0, 2));
        rm1 = fmaxf(rm1, __shfl_xor_sync(0xffffffffu, rm1, 1));
        rm1 = fmaxf(rm1, __shfl_xor_sync(0xffffffffu, rm1, 2));

        const float mn0 = fmaxf(m0, rm0);
        const float mn1 = fmaxf(m1, rm1);
        const float a0 = __expf(m0 - mn0);
        const float a1 = __expf(m1 - mn1);

        float rs0 = 0.0f, rs1 = 0.0f;
        #pragma unroll
        for (int t = 0; t < 8; t++) {
            s[t][0] = __expf(s[t][0] - mn0);
            s[t][1] = __expf(s[t][1] - mn0);
            s[t][2] = __expf(s[t][2] - mn1);
            s[t][3] = __expf(s[t][3] - mn1);
            rs0 += s[t][0] + s[t][1];
            rs1 += s[t][2] + s[t][3];
        }
        rs0 += __shfl_xor_sync(0xffffffffu, rs0, 1);
        rs0 += __shfl_xor_sync(0xffffffffu, rs0, 2);
        rs1 += __shfl_xor_sync(0xffffffffu, rs1, 1);
        rs1 += __shfl_xor_sync(0xffffffffu, rs1, 2);

        l0 = l0 * a0 + rs0;
        l1 = l1 * a1 + rs1;
        m0 = mn0;
        m1 = mn1;
        #pragma unroll
        for (int t = 0; t < 8; t++) {
            acc_o[t][0] *= a0;
            acc_o[t][1] *= a0;
            acc_o[t][2] *= a1;
            acc_o[t][3] *= a1;
        }

        #pragma unroll
        for (int kb = 0; kb < 4; kb++) {
            const int t0 = 2 * kb, t1 = 2 * kb + 1;
            uint32_t pah[4], pal[4];
            split2(s[t0][0], s[t0][1], pah[0], pal[0]);
            split2(s[t0][2], s[t0][3], pah[1], pal[1]);
            split2(s[t1][0], s[t1][1], pah[2], pal[2]);
            split2(s[t1][2], s[t1][3], pah[3], pal[3]);
            #pragma unroll
            for (int t = 0; t < 8; t++) {
                const int n = t * 8 + g;
                uint32_t bh[2], bl[2];
                bh[0] = *reinterpret_cast<const uint32_t*>(Vh + n * AT_LD + kb * 16 + tg * 2);
                bh[1] = *reinterpret_cast<const uint32_t*>(Vh + n * AT_LD + kb * 16 + tg * 2 + 8);
                bl[0] = *reinterpret_cast<const uint32_t*>(Vl + n * AT_LD + kb * 16 + tg * 2);
                bl[1] = *reinterpret_cast<const uint32_t*>(Vl + n * AT_LD + kb * 16 + tg * 2 + 8);
                mma_bf16(acc_o[t], pah, bh);
                mma_bf16(acc_o[t], pah, bl);
                mma_bf16(acc_o[t], pal, bh);
            }
        }
    }

    const float inv0 = 1.0f / l0;
    const float inv1 = 1.0f / l1;
    const int r0g = q0 + wp * 16 + g;
    const size_t row0 = ((size_t)(b * Ss + r0g)) * Ee + h * 64;
    const size_t row1 = ((size_t)(b * Ss + r0g + 8)) * Ee + h * 64;
    #pragma unroll
    for (int t = 0; t < 8; t++) {
        const int c = t * 8 + tg * 2;
        uint32_t hpk, lpk;
        split2(acc_o[t][0] * inv0, acc_o[t][1] * inv0, hpk, lpk);
        *reinterpret_cast<uint32_t*>(g_yh + row0 + c) = hpk;
        *reinterpret_cast<uint32_t*>(g_yl + row0 + c) = lpk;
        split2(acc_o[t][2] * inv1, acc_o[t][3] * inv1, hpk, lpk);
        *reinterpret_cast<uint32_t*>(g_yh + row1 + c) = hpk;
        *reinterpret_cast<uint32_t*>(g_yl + row1 + c) = lpk;
    }
}

// ---------------------------------------------------------------------------
// Kernel 3: proj GEMM — register-staged prefetch.
// ---------------------------------------------------------------------------
__global__ __launch_bounds__(256) void proj_gemm_kernel(
    const float* __restrict__ bias,
    float* __restrict__ out)
{
    __shared__ __nv_bfloat16 Ah[GBM * A_LD];
    __shared__ __nv_bfloat16 Al[GBM * A_LD];
    __shared__ __nv_bfloat16 Bth[GBN * BT_LD];
    __shared__ __nv_bfloat16 Btl[GBN * BT_LD];

    const int tid = threadIdx.x;
    const int m0 = blockIdx.y * GBM;
    const int n0 = blockIdx.x * GBN;

    const int w    = tid >> 5;
    const int wm   = w >> 1;
    const int wn   = w & 1;
    const int lane = tid & 31;
    const int g    = lane >> 2;
    const int tg   = lane & 3;

    const int ar  = tid >> 2;
    const int ac8 = tid & 3;
    const int br  = tid >> 2;
    const int bc8 = tid & 3;

    float acc[2][4][4] = {};
    constexpr int NIT = Kdim / GBK;

    uint4 rAh0, rAh1, rAl0, rAl1, rBh, rBl;
    {
        const size_t a0 = (size_t)(m0 + ar) * Kdim + ac8 * 8;
        const size_t a1 = (size_t)(m0 + ar + 64) * Kdim + ac8 * 8;
        rAh0 = *reinterpret_cast<const uint4*>(g_yh + a0);
        rAh1 = *reinterpret_cast<const uint4*>(g_yh + a1);
        rAl0 = *reinterpret_cast<const uint4*>(g_yl + a0);
        rAl1 = *reinterpret_cast<const uint4*>(g_yl + a1);
        const size_t bo = (size_t)(n0 + br) * Kdim + bc8 * 8;
        rBh = *reinterpret_cast<const uint4*>(g_WpTh + bo);
        rBl = *reinterpret_cast<const uint4*>(g_WpTl + bo);
    }

    for (int it = 0; it < NIT; it++) {
        __syncthreads();
        *reinterpret_cast<uint4*>(Ah + ar * A_LD + ac8 * 8)        = rAh0;
        *reinterpret_cast<uint4*>(Ah + (ar + 64) * A_LD + ac8 * 8) = rAh1;
        *reinterpret_cast<uint4*>(Al + ar * A_LD + ac8 * 8)        = rAl0;
        *reinterpret_cast<uint4*>(Al + (ar + 64) * A_LD + ac8 * 8) = rAl1;
        *reinterpret_cast<uint4*>(Bth + br * BT_LD + bc8 * 8)      = rBh;
        *reinterpret_cast<uint4*>(Btl + br * BT_LD + bc8 * 8)      = rBl;
        __syncthreads();

        if (it + 1 < NIT) {
            const int k0 = (it + 1) * GBK;
            const size_t a0 = (size_t)(m0 + ar) * Kdim + k0 + ac8 * 8;
            const size_t a1 = (size_t)(m0 + ar + 64) * Kdim + k0 + ac8 * 8;
            rAh0 = *reinterpret_cast<const uint4*>(g_yh + a0);
            rAh1 = *reinterpret_cast<const uint4*>(g_yh + a1);
            rAl0 = *reinterpret_cast<const uint4*>(g_yl + a0);
            rAl1 = *reinterpret_cast<const uint4*>(g_yl + a1);
            const size_t bo = (size_t)(n0 + br) * Kdim + k0 + bc8 * 8;
            rBh = *reinterpret_cast<const uint4*>(g_WpTh + bo);
            rBl = *reinterpret_cast<const uint4*>(g_WpTl + bo);
        }

        #pragma unroll
        for (int ks = 0; ks < 2; ks++) {
            const int kk = ks * 16;
            uint32_t ahf[2][4], alf[2][4];
            #pragma unroll
            for (int i = 0; i < 2; i++) {
                const int brr = wm * 32 + i * 16;
                ahf[i][0] = *reinterpret_cast<const uint32_t*>(Ah + (brr + g)     * A_LD + kk + tg * 2);
                ahf[i][1] = *reinterpret_cast<const uint32_t*>(Ah + (brr + g + 8) * A_LD + kk + tg * 2);
                ahf[i][2] = *reinterpret_cast<const uint32_t*>(Ah + (brr + g)     * A_LD + kk + tg * 2 + 8);
                ahf[i][3] = *reinterpret_cast<const uint32_t*>(Ah + (brr + g + 8) * A_LD + kk + tg * 2 + 8);
                alf[i][0] = *reinterpret_cast<const uint32_t*>(Al + (brr + g)     * A_LD + kk + tg * 2);
                alf[i][1] = *reinterpret_cast<const uint32_t*>(Al + (brr + g + 8) * A_LD + kk + tg * 2);
                alf[i][2] = *reinterpret_cast<const uint32_t*>(Al + (brr + g)     * A_LD + kk + tg * 2 + 8);
                alf[i][3] = *reinterpret_cast<const uint32_t*>(Al + (brr + g + 8) * A_LD + kk + tg * 2 + 8);
            }
            uint32_t bhf[4][2], blf[4][2];
            #pragma unroll
            for (int j = 0; j < 4; j++) {
                const int n = wn * 32 + j * 8 + g;
                bhf[j][0] = *reinterpret_cast<const uint32_t*>(Bth + n * BT_LD + kk + tg * 2);
                bhf[j][1] = *reinterpret_cast<const uint32_t*>(Bth + n * BT_LD + kk + tg * 2 + 8);
                blf[j][0] = *reinterpret_cast<const uint32_t*>(Btl + n * BT_LD + kk + tg * 2);
                blf[j][1] = *reinterpret_cast<const uint32_t*>(Btl + n * BT_LD + kk + tg * 2 + 8);
            }
            #pragma unroll
            for (int i = 0; i < 2; i++)
                #pragma unroll
                for (int j = 0; j < 4; j++) {
                    mma_bf16(acc[i][j], ahf[i], bhf[j]);
                    mma_bf16(acc[i][j], ahf[i], blf[j]);
                    mma_bf16(acc[i][j], alf[i], bhf[j]);
                }
        }
    }

    #pragma unroll
    for (int i = 0; i < 2; i++) {
        #pragma unroll
        for (int j = 0; j < 4; j++) {
            const int colb = n0 + wn * 32 + j * 8 + tg * 2;
            #pragma unroll
            for (int e4 = 0; e4 < 4; e4++) {
                const int m = m0 + wm * 32 + i * 16 + g + (e4 >= 2 ? 8 : 0);
                const int n = colb + (e4 & 1);
                out[(size_t)m * Ee + n] = acc[i][j][e4] + bias[n];
            }
        }
    }
}

// ---------------------------------------------------------------------------
// Launch
// ---------------------------------------------------------------------------
extern "C" void kernel_launch(void* const* d_in, const int* in_sizes, int n_in,
                              void* d_out, int out_size)
{
    const float* x      = (const float*)d_in[0];  // [B,S,E]
    const float* W_attn = (const float*)d_in[1];  // [E,3E]
    const float* b_attn = (const float*)d_in[2];  // [3E]
    const float* W_proj = (const float*)d_in[3];  // [E,E]
    const float* b_proj = (const float*)d_in[4];  // [E]
    const int* att_mask = (const int*)d_in[5];    // [B,S]
    float* out = (float*)d_out;

    cudaFuncSetAttribute(attn_kernel,
                         cudaFuncAttributeMaxDynamicSharedMemorySize,
                         (int)ATT_SMEM_BYTES);

    split_x_kernel<<<(Mrows * Kdim) / 2048, 256>>>(x);
    {
        dim3 grid(N_QKV / 32, Kdim / 32);      // 72 x 24
        split_wa_kernel<<<grid, 256>>>(W_attn);
    }
    {
        dim3 grid(Ee / 32, Kdim / 32);         // 24 x 24
        split_wp_kernel<<<grid, 256>>>(W_proj);
    }
    {
        dim3 grid(N_QKV / GBN, Mrows / GBM);   // 36 x 64
        qkv_gemm_kernel<<<grid, 256>>>(b_attn);
    }
    {
        dim3 grid(Ss / QROWS, Hh, Bb);         // 16 x 12 x 4
        attn_kernel<<<grid, 256, ATT_SMEM_BYTES>>>(att_mask);
    }
    {
        dim3 grid(Ee / GBN, Mrows / GBM);      // 12 x 64
        proj_gemm_kernel<<<grid, 256>>>(b_proj, out);
    }
}